// round 3
// baseline (speedup 1.0000x reference)
#include <cuda_runtime.h>
#include <cuda_bf16.h>
#include <math.h>
#include <stdint.h>

#define LL 512
#define DS 256
#define HH 32
#define DP 128
#define KRBF 36
#define K2 48          // padded rbf K

// ---------------- scratch globals ----------------
__device__ float    g_left[LL * HH];
__device__ float    g_right[LL * HH];      // [m][32] fp32
__device__ float    g_cas[LL * 4];
__device__ uint32_t g_tp_hi[LL * DP * 16]; // t^T bf16 hi: [l][p][16 words = 32 k]
__device__ uint32_t g_tp_lo[LL * DP * 16];
__device__ uint32_t g_wr_hi[DP * 24];      // w_rbf^T bf16 hi: [p][24 words = 48 k]
__device__ uint32_t g_wr_lo[DP * 24];

// ---------------- helpers ----------------
__device__ __forceinline__ uint32_t smem_u32(const void* p) {
    uint32_t a;
    asm("{ .reg .u64 t; cvta.to.shared.u64 t, %1; cvt.u32.u64 %0, t; }" : "=r"(a) : "l"(p));
    return a;
}
// pack two fp32 -> bf16x2 (v0 -> low half / even k, v1 -> high half / odd k)
__device__ __forceinline__ uint32_t bpack(float v0, float v1) {
    uint32_t r;
    asm("cvt.rn.bf16x2.f32 %0, %1, %2;" : "=r"(r) : "f"(v1), "f"(v0));
    return r;
}
__device__ __forceinline__ float bhi(float x) {
    return __bfloat162float(__float2bfloat16(x));
}
__device__ __forceinline__ void mma16816(float d[4], const uint32_t a[4], const uint32_t b[2]) {
    asm volatile("mma.sync.aligned.m16n8k16.row.col.f32.bf16.bf16.f32 "
        "{%0,%1,%2,%3}, {%4,%5,%6,%7}, {%8,%9}, {%0,%1,%2,%3};"
        : "+f"(d[0]), "+f"(d[1]), "+f"(d[2]), "+f"(d[3])
        : "r"(a[0]), "r"(a[1]), "r"(a[2]), "r"(a[3]), "r"(b[0]), "r"(b[1]));
}
__device__ __forceinline__ void ldmx4(uint32_t r[4], uint32_t addr) {
    asm volatile("ldmatrix.sync.aligned.m8n8.x4.shared.b16 {%0,%1,%2,%3}, [%4];"
        : "=r"(r[0]), "=r"(r[1]), "=r"(r[2]), "=r"(r[3]) : "r"(addr));
}
__device__ __forceinline__ float sigmoidf_(float x) {
    return __fdividef(1.0f, 1.0f + __expf(-x));
}

// ---------------------------------------------------------------------------
// k_prep: LayerNorm + left/right projections + cas
// ---------------------------------------------------------------------------
__global__ __launch_bounds__(256) void k_prep(
    const float* __restrict__ xyz, const float* __restrict__ state,
    const float* __restrict__ ln_w, const float* __restrict__ ln_b,
    const float* __restrict__ w_left, const float* __restrict__ b_left,
    const float* __restrict__ w_right, const float* __restrict__ b_right)
{
    int l = blockIdx.x, tid = threadIdx.x;
    __shared__ float st_s[DS];
    __shared__ float red[18];
    __shared__ float part[64][4];

    float x = state[l * DS + tid];
    float s = x, q = x * x;
    #pragma unroll
    for (int o = 16; o; o >>= 1) {
        s += __shfl_xor_sync(0xFFFFFFFFu, s, o);
        q += __shfl_xor_sync(0xFFFFFFFFu, q, o);
    }
    int wid = tid >> 5, lane = tid & 31;
    if (lane == 0) { red[wid] = s; red[8 + wid] = q; }
    __syncthreads();
    if (tid == 0) {
        float S = 0.f, Q = 0.f;
        #pragma unroll
        for (int i = 0; i < 8; i++) { S += red[i]; Q += red[8 + i]; }
        float mu = S * (1.0f / DS);
        float var = Q * (1.0f / DS) - mu * mu;
        red[16] = mu; red[17] = rsqrtf(var + 1e-5f);
    }
    __syncthreads();
    st_s[tid] = (x - red[16]) * red[17] * ln_w[tid] + ln_b[tid];
    __syncthreads();

    {
        int j = tid & 31, half = (tid >> 5) & 1, seg = tid >> 6;
        const float* w = half ? w_right : w_left;
        float acc = 0.f;
        int i0 = seg * 64;
        #pragma unroll 8
        for (int i = 0; i < 64; i++) acc += st_s[i0 + i] * w[(i0 + i) * HH + j];
        part[half * 32 + j][seg] = acc;
    }
    __syncthreads();
    if (tid < 64) {
        int j = tid & 31, half = tid >> 5;
        float a = part[tid][0] + part[tid][1] + part[tid][2] + part[tid][3]
                + (half ? b_right[j] : b_left[j]);
        if (half) g_right[l * HH + j] = a;
        else      g_left[l * HH + j] = a;
    }
    if (tid < 3) g_cas[l * 4 + tid] = xyz[l * 9 + 3 + tid];
}

// ---------------------------------------------------------------------------
// k_t: t[l,k,p] = sum_i left[l,i]*Wg[i,k,p]; emit transposed bf16 hi/lo [l][p][k]
// ---------------------------------------------------------------------------
__global__ __launch_bounds__(128) void k_t(const float* __restrict__ w_gate)
{
    extern __shared__ float tbuf[];   // [8][32][128]
    __shared__ float ls[8 * HH];
    int lb = blockIdx.x * 8, p = threadIdx.x;
    for (int i = p; i < 8 * HH; i += 128) ls[i] = g_left[lb * HH + i];
    __syncthreads();

    for (int j = 0; j < HH; j++) {
        float acc[8];
        #pragma unroll
        for (int lt = 0; lt < 8; lt++) acc[lt] = 0.f;
        #pragma unroll
        for (int i = 0; i < HH; i++) {
            float wv = w_gate[(i * HH + j) * DP + p];
            #pragma unroll
            for (int lt = 0; lt < 8; lt++) acc[lt] += ls[lt * HH + i] * wv;
        }
        #pragma unroll
        for (int lt = 0; lt < 8; lt++) tbuf[(lt * HH + j) * DP + p] = acc[lt];
    }
    __syncthreads();

    for (int lt = 0; lt < 8; lt++) {
        const float* tb = tbuf + lt * HH * DP;
        uint32_t hw[16], lw[16];
        #pragma unroll
        for (int c = 0; c < 16; c++) {
            float v0 = tb[(2 * c) * DP + p], v1 = tb[(2 * c + 1) * DP + p];
            hw[c] = bpack(v0, v1);
            lw[c] = bpack(v0 - bhi(v0), v1 - bhi(v1));
        }
        uint32_t base = (uint32_t)((lb + lt) * DP + p) * 16u;
        uint4* dh = (uint4*)(g_tp_hi + base);
        uint4* dl = (uint4*)(g_tp_lo + base);
        #pragma unroll
        for (int q = 0; q < 4; q++) {
            dh[q] = make_uint4(hw[4*q], hw[4*q+1], hw[4*q+2], hw[4*q+3]);
            dl[q] = make_uint4(lw[4*q], lw[4*q+1], lw[4*q+2], lw[4*q+3]);
        }
    }
}

// ---------------------------------------------------------------------------
// k_wrbf: w_rbf^T bf16 hi/lo, [p][48] (pad 36..47 with 0)
// ---------------------------------------------------------------------------
__global__ void k_wrbf(const float* __restrict__ w_rbf)
{
    int p = threadIdx.x;
    #pragma unroll
    for (int c = 0; c < 24; c++) {
        int k0 = 2 * c, k1 = 2 * c + 1;
        float v0 = (k0 < KRBF) ? w_rbf[k0 * DP + p] : 0.f;
        float v1 = (k1 < KRBF) ? w_rbf[k1 * DP + p] : 0.f;
        g_wr_hi[p * 24 + c] = bpack(v0, v1);
        g_wr_lo[p * 24 + c] = bpack(v0 - bhi(v0), v1 - bhi(v1));
    }
}

// ---------------------------------------------------------------------------
// k_main: mma.sync bf16-split. Block = (l, 64 m) x 128 p, 8 warps.
// Warp tile: 16 m x 64 p. A = right/rbf [m][k], B = t^T / w_rbf^T [p][k].
// Smem layout (padded strides, conflict-free for ldmatrix):
//   A1 (right):  64 x stride 80B  (32 k bf16 + pad)   hi/lo
//   A2 (rbf):    64 x stride 112B (48 k bf16 + pad)   hi/lo
//   B1 (t^T):   128 x stride 80B                      hi/lo
//   B2 (wrbf^T):128 x stride 112B                     hi/lo
// ---------------------------------------------------------------------------
#define A1Ho 0
#define A1Lo 5120
#define A2Ho 10240
#define A2Lo 17408
#define B1Ho 24576
#define B1Lo 34816
#define B2Ho 45056
#define B2Lo 59392
#define SMTOT 73728

__global__ __launch_bounds__(256) void k_main(
    const float* __restrict__ b_rbf, const float* __restrict__ b_gate,
    float* __restrict__ out)
{
    extern __shared__ char smem[];
    __shared__ float dist_s[64];
    uint32_t sb = smem_u32(smem);
    int tid = threadIdx.x, lane = tid & 31, wid = tid >> 5;
    int l = blockIdx.x, mb = blockIdx.y * 64;

    // distances for this m-chunk
    if (tid < 64) {
        int m = mb + tid;
        float dx = g_cas[m * 4]     - g_cas[l * 4];
        float dy = g_cas[m * 4 + 1] - g_cas[l * 4 + 1];
        float dz = g_cas[m * 4 + 2] - g_cas[l * 4 + 2];
        dist_s[tid] = sqrtf(fmaxf(dx * dx + dy * dy + dz * dz, 1e-12f));
    }

    // A1 fill: right -> bf16 hi/lo [64][stride 80B]
    {
        int row = tid >> 2, ch = tid & 3;
        const float4* src = (const float4*)(g_right + (mb + row) * HH + ch * 8);
        float4 x = src[0], y = src[1];
        uint4 h = make_uint4(bpack(x.x, x.y), bpack(x.z, x.w),
                             bpack(y.x, y.y), bpack(y.z, y.w));
        uint4 lo = make_uint4(bpack(x.x - bhi(x.x), x.y - bhi(x.y)),
                              bpack(x.z - bhi(x.z), x.w - bhi(x.w)),
                              bpack(y.x - bhi(y.x), y.y - bhi(y.y)),
                              bpack(y.z - bhi(y.z), y.w - bhi(y.w)));
        *(uint4*)(smem + A1Ho + row * 80 + ch * 16) = h;
        *(uint4*)(smem + A1Lo + row * 80 + ch * 16) = lo;
    }
    // B1 fill: t^T hi/lo copy, [128][stride 80B]
    #pragma unroll
    for (int it = 0; it < 2; it++) {
        int idx = it * 256 + tid;
        int row = idx >> 2, ch = idx & 3;
        uint32_t gb = (uint32_t)(l * DP + row) * 16u + ch * 4;
        *(uint4*)(smem + B1Ho + row * 80 + ch * 16) = *(const uint4*)(g_tp_hi + gb);
        *(uint4*)(smem + B1Lo + row * 80 + ch * 16) = *(const uint4*)(g_tp_lo + gb);
    }
    // B2 fill: w_rbf^T hi/lo copy, [128][stride 112B]
    #pragma unroll
    for (int it = 0; it < 3; it++) {
        int idx = it * 256 + tid;
        int row = idx / 6, ch = idx - row * 6;
        *(uint4*)(smem + B2Ho + row * 112 + ch * 16) = *(const uint4*)(g_wr_hi + row * 24 + ch * 4);
        *(uint4*)(smem + B2Lo + row * 112 + ch * 16) = *(const uint4*)(g_wr_lo + row * 24 + ch * 4);
    }
    __syncthreads();

    // A2 fill: rbf features bf16 hi/lo [64][stride 112B]
    {
        int m = tid >> 2, kg = tid & 3;
        float dist = dist_s[m];
        const float DMU = 20.0f / 35.0f, INV_SIG = 36.0f / 20.0f;
        __nv_bfloat16* rh = (__nv_bfloat16*)(smem + A2Ho + m * 112);
        __nv_bfloat16* rl = (__nv_bfloat16*)(smem + A2Lo + m * 112);
        #pragma unroll
        for (int kk = 0; kk < 12; kk++) {
            int k = kg * 12 + kk;
            float e = 0.f;
            if (k < KRBF) {
                float u = (dist - (2.0f + (float)k * DMU)) * INV_SIG;
                e = __expf(-u * u);
            }
            __nv_bfloat16 h = __float2bfloat16(e);
            rh[k] = h;
            rl[k] = __float2bfloat16(e - __bfloat162float(h));
        }
    }
    __syncthreads();

    // ---- ldmatrix address components ----
    uint32_t rr = lane & 7, q = lane >> 3;
    uint32_t a_r = (q & 1) << 3, a_k = (q >> 1) << 3;   // A quads
    uint32_t b_r = (q >> 1) << 3, b_k = (q & 1) << 3;   // B quads (x4 = 2 n-tiles)
    int M0 = (wid & 3) * 16, P0 = (wid >> 2) * 64;

    // ---- pass 1: logits (K=32) ----
    uint32_t Ah[2][4], Al[2][4];
    #pragma unroll
    for (int ks = 0; ks < 2; ks++) {
        uint32_t ad = sb + A1Ho + (M0 + rr + a_r) * 80 + (ks * 16 + a_k) * 2;
        ldmx4(Ah[ks], ad);
        ldmx4(Al[ks], ad + (A1Lo - A1Ho));
    }
    float accL[8][4];
    #pragma unroll
    for (int i = 0; i < 8; i++)
        #pragma unroll
        for (int j = 0; j < 4; j++) accL[i][j] = 0.f;

    #pragma unroll
    for (int np = 0; np < 4; np++) {
        int n0 = P0 + np * 16;
        uint32_t bbase = sb + B1Ho + (n0 + rr + b_r) * 80 + b_k * 2;
        #pragma unroll
        for (int ks = 0; ks < 2; ks++) {
            uint32_t bh[4], bl[4];
            ldmx4(bh, bbase + ks * 32);
            ldmx4(bl, bbase + ks * 32 + (B1Lo - B1Ho));
            mma16816(accL[2*np],   Ah[ks], bh);
            mma16816(accL[2*np],   Ah[ks], bl);
            mma16816(accL[2*np],   Al[ks], bh);
            mma16816(accL[2*np+1], Ah[ks], bh + 2);
            mma16816(accL[2*np+1], Ah[ks], bl + 2);
            mma16816(accL[2*np+1], Al[ks], bh + 2);
        }
    }

    // ---- pass 2: feat (K=48) + fused epilogue ----
    uint32_t Fh[3][4], Fl[3][4];
    #pragma unroll
    for (int ks = 0; ks < 3; ks++) {
        uint32_t ad = sb + A2Ho + (M0 + rr + a_r) * 112 + (ks * 16 + a_k) * 2;
        ldmx4(Fh[ks], ad);
        ldmx4(Fl[ks], ad + (A2Lo - A2Ho));
    }
    int r0 = lane >> 2, c2 = (lane & 3) * 2;

    #pragma unroll
    for (int np = 0; np < 4; np++) {
        int n0 = P0 + np * 16;
        uint32_t bbase = sb + B2Ho + (n0 + rr + b_r) * 112 + b_k * 2;
        float accF[2][4];
        #pragma unroll
        for (int i = 0; i < 2; i++)
            #pragma unroll
            for (int j = 0; j < 4; j++) accF[i][j] = 0.f;
        #pragma unroll
        for (int ks = 0; ks < 3; ks++) {
            uint32_t bh[4], bl[4];
            ldmx4(bh, bbase + ks * 32);
            ldmx4(bl, bbase + ks * 32 + (B2Lo - B2Ho));
            mma16816(accF[0], Fh[ks], bh);
            mma16816(accF[0], Fh[ks], bl);
            mma16816(accF[0], Fl[ks], bh);
            mma16816(accF[1], Fh[ks], bh + 2);
            mma16816(accF[1], Fh[ks], bl + 2);
            mma16816(accF[1], Fl[ks], bh + 2);
        }
        // epilogue for the two n-tiles of this pair
        #pragma unroll
        for (int e = 0; e < 2; e++) {
            int nt = 2 * np + e;
            int p = P0 + nt * 8 + c2;
            float2 bg = *(const float2*)(b_gate + p);
            float2 br = *(const float2*)(b_rbf + p);
            const float* Lc = accL[nt];
            const float* Fc = accF[e];
            int m0 = mb + M0 + r0;
            float* o0 = out + ((size_t)l * LL + m0) * DP + p;
            float2 v0, v1;
            v0.x = (Fc[0] + br.x) * sigmoidf_(Lc[0] + bg.x);
            v0.y = (Fc[1] + br.y) * sigmoidf_(Lc[1] + bg.y);
            v1.x = (Fc[2] + br.x) * sigmoidf_(Lc[2] + bg.x);
            v1.y = (Fc[3] + br.y) * sigmoidf_(Lc[3] + bg.y);
            *(float2*)o0 = v0;
            *(float2*)(o0 + 8 * DP) = v1;
        }
    }
}

// ---------------------------------------------------------------------------
extern "C" void kernel_launch(void* const* d_in, const int* in_sizes, int n_in,
                              void* d_out, int out_size)
{
    const float* xyz     = (const float*)d_in[0];
    const float* state   = (const float*)d_in[1];
    const float* ln_w    = (const float*)d_in[2];
    const float* ln_b    = (const float*)d_in[3];
    const float* w_rbf   = (const float*)d_in[4];
    const float* b_rbf   = (const float*)d_in[5];
    const float* w_left  = (const float*)d_in[6];
    const float* b_left  = (const float*)d_in[7];
    const float* w_right = (const float*)d_in[8];
    const float* b_right = (const float*)d_in[9];
    const float* w_gate  = (const float*)d_in[10];
    const float* b_gate  = (const float*)d_in[11];
    float* out = (float*)d_out;

    k_prep<<<LL, 256>>>(xyz, state, ln_w, ln_b, w_left, b_left, w_right, b_right);

    int smem_t = 8 * HH * DP * (int)sizeof(float);   // 128 KB
    cudaFuncSetAttribute(k_t, cudaFuncAttributeMaxDynamicSharedMemorySize, smem_t);
    k_t<<<64, 128, smem_t>>>(w_gate);

    k_wrbf<<<1, 128>>>(w_rbf);

    cudaFuncSetAttribute(k_main, cudaFuncAttributeMaxDynamicSharedMemorySize, SMTOT);
    k_main<<<dim3(LL, 8), 256, SMTOT>>>(b_rbf, b_gate, out);
}

// round 4
// speedup vs baseline: 1.6424x; 1.6424x over previous
#include <cuda_runtime.h>
#include <cuda_fp16.h>
#include <math.h>
#include <stdint.h>

#define LL 512
#define DS 256
#define HH 32
#define DP 128
#define KRBF 36

// ---------------- scratch globals ----------------
__device__ float    g_left[LL * HH];
__device__ float    g_right[LL * HH];      // [m][32] fp32
__device__ float    g_cas[LL * 4];
__device__ uint32_t g_tp_hi[LL * DP * 16]; // t^T fp16 hi: [l][p][16 words = 32 k]
__device__ uint32_t g_tp_lo[LL * DP * 16];
__device__ uint32_t g_wr_hi[DP * 24];      // w_rbf^T fp16 hi: [p][24 words = 48 k]
__device__ uint32_t g_wr_lo[DP * 24];

// ---------------- helpers ----------------
__device__ __forceinline__ uint32_t smem_u32(const void* p) {
    uint32_t a;
    asm("{ .reg .u64 t; cvta.to.shared.u64 t, %1; cvt.u32.u64 %0, t; }" : "=r"(a) : "l"(p));
    return a;
}
__device__ __forceinline__ uint32_t pk2(float a, float b) {
    __half2 h = __floats2half2_rn(a, b);
    return *(uint32_t*)&h;
}
__device__ __forceinline__ float hf(float x) {
    return __half2float(__float2half_rn(x));
}
__device__ __forceinline__ void mma16816(float d[4], const uint32_t a[4], const uint32_t b[2]) {
    asm volatile("mma.sync.aligned.m16n8k16.row.col.f32.f16.f16.f32 "
        "{%0,%1,%2,%3}, {%4,%5,%6,%7}, {%8,%9}, {%0,%1,%2,%3};"
        : "+f"(d[0]), "+f"(d[1]), "+f"(d[2]), "+f"(d[3])
        : "r"(a[0]), "r"(a[1]), "r"(a[2]), "r"(a[3]), "r"(b[0]), "r"(b[1]));
}
__device__ __forceinline__ void ldmx4(uint32_t r[4], uint32_t addr) {
    asm volatile("ldmatrix.sync.aligned.m8n8.x4.shared.b16 {%0,%1,%2,%3}, [%4];"
        : "=r"(r[0]), "=r"(r[1]), "=r"(r[2]), "=r"(r[3]) : "r"(addr));
}
__device__ __forceinline__ float sigmoidf_(float x) {
    return __fdividef(1.0f, 1.0f + __expf(-x));
}

// ---------------------------------------------------------------------------
// k_prep: LayerNorm + left/right projections + cas; block 0 also packs w_rbf^T
// ---------------------------------------------------------------------------
__global__ __launch_bounds__(256) void k_prep(
    const float* __restrict__ xyz, const float* __restrict__ state,
    const float* __restrict__ ln_w, const float* __restrict__ ln_b,
    const float* __restrict__ w_left, const float* __restrict__ b_left,
    const float* __restrict__ w_right, const float* __restrict__ b_right,
    const float* __restrict__ w_rbf)
{
    int l = blockIdx.x, tid = threadIdx.x;
    __shared__ float st_s[DS];
    __shared__ float red[18];
    __shared__ float part[64][4];

    float x = state[l * DS + tid];
    float s = x, q = x * x;
    #pragma unroll
    for (int o = 16; o; o >>= 1) {
        s += __shfl_xor_sync(0xFFFFFFFFu, s, o);
        q += __shfl_xor_sync(0xFFFFFFFFu, q, o);
    }
    int wid = tid >> 5, lane = tid & 31;
    if (lane == 0) { red[wid] = s; red[8 + wid] = q; }
    __syncthreads();
    if (tid == 0) {
        float S = 0.f, Q = 0.f;
        #pragma unroll
        for (int i = 0; i < 8; i++) { S += red[i]; Q += red[8 + i]; }
        float mu = S * (1.0f / DS);
        float var = Q * (1.0f / DS) - mu * mu;
        red[16] = mu; red[17] = rsqrtf(var + 1e-5f);
    }
    __syncthreads();
    st_s[tid] = (x - red[16]) * red[17] * ln_w[tid] + ln_b[tid];
    __syncthreads();

    {
        int j = tid & 31, half = (tid >> 5) & 1, seg = tid >> 6;
        const float* w = half ? w_right : w_left;
        float acc = 0.f;
        int i0 = seg * 64;
        #pragma unroll 8
        for (int i = 0; i < 64; i++) acc += st_s[i0 + i] * w[(i0 + i) * HH + j];
        part[half * 32 + j][seg] = acc;
    }
    __syncthreads();
    if (tid < 64) {
        int j = tid & 31, half = tid >> 5;
        float a = part[tid][0] + part[tid][1] + part[tid][2] + part[tid][3]
                + (half ? b_right[j] : b_left[j]);
        if (half) g_right[l * HH + j] = a;
        else      g_left[l * HH + j] = a;
    }
    if (tid < 3) g_cas[l * 4 + tid] = xyz[l * 9 + 3 + tid];

    // block 0: pack w_rbf^T fp16 hi/lo [p][48 k] (pad 36..47 = 0)
    if (blockIdx.x == 0 && tid < DP) {
        #pragma unroll
        for (int c = 0; c < 24; c++) {
            int k0 = 2 * c, k1 = 2 * c + 1;
            float v0 = (k0 < KRBF) ? w_rbf[k0 * DP + tid] : 0.f;
            float v1 = (k1 < KRBF) ? w_rbf[k1 * DP + tid] : 0.f;
            g_wr_hi[tid * 24 + c] = pk2(v0, v1);
            g_wr_lo[tid * 24 + c] = pk2(v0 - hf(v0), v1 - hf(v1));
        }
    }
}

// ---------------------------------------------------------------------------
// k_t: t[l,k,p] = sum_i left[l,i]*Wg[i,k,p]; emit t^T fp16 hi/lo [l][p][k]
// grid = (64 lb, 4 jb): 8 l x 8 j x 128 p per block, 128 threads
// ---------------------------------------------------------------------------
__global__ __launch_bounds__(128) void k_t(const float* __restrict__ w_gate)
{
    __shared__ float ls[8 * HH];
    int lb = blockIdx.x * 8, jb = blockIdx.y * 8, p = threadIdx.x;
    for (int i = p; i < 8 * HH; i += 128) ls[i] = g_left[lb * HH + i];
    __syncthreads();

    #pragma unroll
    for (int jj = 0; jj < 2; jj++) {
        float acc[8][4];
        #pragma unroll
        for (int lt = 0; lt < 8; lt++)
            #pragma unroll
            for (int qj = 0; qj < 4; qj++) acc[lt][qj] = 0.f;

        #pragma unroll
        for (int i = 0; i < HH; i++) {
            float wv[4];
            #pragma unroll
            for (int qj = 0; qj < 4; qj++)
                wv[qj] = w_gate[(i * HH + jb + jj * 4 + qj) * DP + p];
            #pragma unroll
            for (int lt = 0; lt < 8; lt++) {
                float lv = ls[lt * HH + i];
                #pragma unroll
                for (int qj = 0; qj < 4; qj++) acc[lt][qj] += lv * wv[qj];
            }
        }
        int c0 = jb / 2 + jj * 2;   // word index within 16
        #pragma unroll
        for (int lt = 0; lt < 8; lt++) {
            uint32_t h0 = pk2(acc[lt][0], acc[lt][1]);
            uint32_t h1 = pk2(acc[lt][2], acc[lt][3]);
            uint32_t l0 = pk2(acc[lt][0] - hf(acc[lt][0]), acc[lt][1] - hf(acc[lt][1]));
            uint32_t l1 = pk2(acc[lt][2] - hf(acc[lt][2]), acc[lt][3] - hf(acc[lt][3]));
            uint32_t base = (uint32_t)((lb + lt) * DP + p) * 16u + c0;
            *(uint2*)(g_tp_hi + base) = make_uint2(h0, h1);
            *(uint2*)(g_tp_lo + base) = make_uint2(l0, l1);
        }
    }
}

// ---------------------------------------------------------------------------
// k_main: mma.sync fp16 2-product split. Block = (l, 64 m) x 128 p, 8 warps.
// Warp tile 32m x 32p (m-group = wid&1, p-group = wid>>1).
// A (m-side, hi only): A1 = right [64][80B], A2 = rbf [64][112B]
// B (p-side, hi+lo):   B1 = t^T [128][80B], B2 = wrbf^T [128][112B]
// ---------------------------------------------------------------------------
#define A1H 0
#define A2H 5120
#define B1H 12288
#define B1L 22528
#define B2H 32768
#define B2L 47104
#define SMTOT 61440

__global__ __launch_bounds__(256) void k_main(
    const float* __restrict__ b_rbf, const float* __restrict__ b_gate,
    float* __restrict__ out)
{
    extern __shared__ char smem[];
    __shared__ float dist_s[64];
    uint32_t sb = smem_u32(smem);
    int tid = threadIdx.x, lane = tid & 31, wid = tid >> 5;
    int l = blockIdx.x, mb = blockIdx.y * 64;

    if (tid < 64) {
        int m = mb + tid;
        float dx = g_cas[m * 4]     - g_cas[l * 4];
        float dy = g_cas[m * 4 + 1] - g_cas[l * 4 + 1];
        float dz = g_cas[m * 4 + 2] - g_cas[l * 4 + 2];
        dist_s[tid] = sqrtf(fmaxf(dx * dx + dy * dy + dz * dz, 1e-12f));
    }

    // A1 fill: right -> fp16 hi [64][80B]
    {
        int row = tid >> 2, ch = tid & 3;
        const float4* src = (const float4*)(g_right + (mb + row) * HH + ch * 8);
        float4 x = src[0], y = src[1];
        uint4 h = make_uint4(pk2(x.x, x.y), pk2(x.z, x.w), pk2(y.x, y.y), pk2(y.z, y.w));
        *(uint4*)(smem + A1H + row * 80 + ch * 16) = h;
    }
    // B1 fill: t^T hi/lo [128][80B]
    #pragma unroll
    for (int it = 0; it < 2; it++) {
        int idx = it * 256 + tid;
        int row = idx >> 2, ch = idx & 3;
        uint32_t gb = (uint32_t)(l * DP + row) * 16u + ch * 4;
        *(uint4*)(smem + B1H + row * 80 + ch * 16) = *(const uint4*)(g_tp_hi + gb);
        *(uint4*)(smem + B1L + row * 80 + ch * 16) = *(const uint4*)(g_tp_lo + gb);
    }
    // B2 fill: w_rbf^T hi/lo [128][112B]
    #pragma unroll
    for (int it = 0; it < 3; it++) {
        int idx = it * 256 + tid;
        int row = idx / 6, ch = idx - row * 6;
        *(uint4*)(smem + B2H + row * 112 + ch * 16) = *(const uint4*)(g_wr_hi + row * 24 + ch * 4);
        *(uint4*)(smem + B2L + row * 112 + ch * 16) = *(const uint4*)(g_wr_lo + row * 24 + ch * 4);
    }
    __syncthreads();

    // A2 fill: rbf features fp16 hi [64][112B]
    {
        int m = tid >> 2, kg = tid & 3;
        float dist = dist_s[m];
        const float DMU = 20.0f / 35.0f, INV_SIG = 36.0f / 20.0f;
        #pragma unroll
        for (int kk = 0; kk < 6; kk++) {
            int k = kg * 12 + 2 * kk;
            float e0 = 0.f, e1 = 0.f;
            if (k < KRBF) {
                float u = (dist - (2.0f + (float)k * DMU)) * INV_SIG;
                e0 = __expf(-u * u);
            }
            if (k + 1 < KRBF) {
                float u = (dist - (2.0f + (float)(k + 1) * DMU)) * INV_SIG;
                e1 = __expf(-u * u);
            }
            *(uint32_t*)(smem + A2H + m * 112 + k * 2) = pk2(e0, e1);
        }
    }
    __syncthreads();

    // ---- ldmatrix address components (validated in R3) ----
    uint32_t rr = lane & 7, q = lane >> 3;
    uint32_t a_r = (q & 1) << 3, a_k = (q >> 1) << 3;   // A x4 quads
    uint32_t b_r = (q >> 1) << 3, b_k = (q & 1) << 3;   // B x4 quads (2 n-tiles)
    int M0 = (wid & 1) * 32, P0 = (wid >> 1) * 32;

    // ---- pass 1: logits (K=32, 2 ks) ----
    uint32_t Ah[2][2][4];
    #pragma unroll
    for (int mt = 0; mt < 2; mt++)
        #pragma unroll
        for (int ks = 0; ks < 2; ks++)
            ldmx4(Ah[mt][ks], sb + A1H + (M0 + mt * 16 + rr + a_r) * 80 + (ks * 16 + a_k) * 2);

    float accL[2][4][4];
    #pragma unroll
    for (int mt = 0; mt < 2; mt++)
        #pragma unroll
        for (int nt = 0; nt < 4; nt++)
            #pragma unroll
            for (int j = 0; j < 4; j++) accL[mt][nt][j] = 0.f;

    #pragma unroll
    for (int npp = 0; npp < 2; npp++) {
        int n0 = P0 + npp * 16;
        uint32_t bbase = sb + B1H + (n0 + rr + b_r) * 80 + b_k * 2;
        #pragma unroll
        for (int ks = 0; ks < 2; ks++) {
            uint32_t bh[4], bl[4];
            ldmx4(bh, bbase + ks * 32);
            ldmx4(bl, bbase + ks * 32 + (B1L - B1H));
            #pragma unroll
            for (int mt = 0; mt < 2; mt++) {
                mma16816(accL[mt][2 * npp],     Ah[mt][ks], bh);
                mma16816(accL[mt][2 * npp],     Ah[mt][ks], bl);
                mma16816(accL[mt][2 * npp + 1], Ah[mt][ks], bh + 2);
                mma16816(accL[mt][2 * npp + 1], Ah[mt][ks], bl + 2);
            }
        }
    }

    // ---- pass 2: feat (K=48, 3 ks) + fused epilogue ----
    uint32_t Fh[2][3][4];
    #pragma unroll
    for (int mt = 0; mt < 2; mt++)
        #pragma unroll
        for (int ks = 0; ks < 3; ks++)
            ldmx4(Fh[mt][ks], sb + A2H + (M0 + mt * 16 + rr + a_r) * 112 + (ks * 16 + a_k) * 2);

    int r0 = lane >> 2, c2 = (lane & 3) * 2;

    #pragma unroll
    for (int npp = 0; npp < 2; npp++) {
        int n0 = P0 + npp * 16;
        uint32_t bbase = sb + B2H + (n0 + rr + b_r) * 112 + b_k * 2;
        float accF[2][2][4];
        #pragma unroll
        for (int mt = 0; mt < 2; mt++)
            #pragma unroll
            for (int nt = 0; nt < 2; nt++)
                #pragma unroll
                for (int j = 0; j < 4; j++) accF[mt][nt][j] = 0.f;
        #pragma unroll
        for (int ks = 0; ks < 3; ks++) {
            uint32_t bh[4], bl[4];
            ldmx4(bh, bbase + ks * 32);
            ldmx4(bl, bbase + ks * 32 + (B2L - B2H));
            #pragma unroll
            for (int mt = 0; mt < 2; mt++) {
                mma16816(accF[mt][0], Fh[mt][ks], bh);
                mma16816(accF[mt][0], Fh[mt][ks], bl);
                mma16816(accF[mt][1], Fh[mt][ks], bh + 2);
                mma16816(accF[mt][1], Fh[mt][ks], bl + 2);
            }
        }
        // epilogue
        #pragma unroll
        for (int mt = 0; mt < 2; mt++) {
            #pragma unroll
            for (int ntl = 0; ntl < 2; ntl++) {
                int p = P0 + npp * 16 + ntl * 8 + c2;
                float2 bg = *(const float2*)(b_gate + p);
                float2 br = *(const float2*)(b_rbf + p);
                const float* Lc = accL[mt][2 * npp + ntl];
                const float* Fc = accF[mt][ntl];
                int m0 = mb + M0 + mt * 16 + r0;
                float* o0 = out + ((size_t)l * LL + m0) * DP + p;
                float2 v0, v1;
                v0.x = (Fc[0] + br.x) * sigmoidf_(Lc[0] + bg.x);
                v0.y = (Fc[1] + br.y) * sigmoidf_(Lc[1] + bg.y);
                v1.x = (Fc[2] + br.x) * sigmoidf_(Lc[2] + bg.x);
                v1.y = (Fc[3] + br.y) * sigmoidf_(Lc[3] + bg.y);
                *(float2*)o0 = v0;
                *(float2*)(o0 + 8 * DP) = v1;
            }
        }
    }
}

// ---------------------------------------------------------------------------
extern "C" void kernel_launch(void* const* d_in, const int* in_sizes, int n_in,
                              void* d_out, int out_size)
{
    const float* xyz     = (const float*)d_in[0];
    const float* state   = (const float*)d_in[1];
    const float* ln_w    = (const float*)d_in[2];
    const float* ln_b    = (const float*)d_in[3];
    const float* w_rbf   = (const float*)d_in[4];
    const float* b_rbf   = (const float*)d_in[5];
    const float* w_left  = (const float*)d_in[6];
    const float* b_left  = (const float*)d_in[7];
    const float* w_right = (const float*)d_in[8];
    const float* b_right = (const float*)d_in[9];
    const float* w_gate  = (const float*)d_in[10];
    const float* b_gate  = (const float*)d_in[11];
    float* out = (float*)d_out;

    k_prep<<<LL, 256>>>(xyz, state, ln_w, ln_b, w_left, b_left, w_right, b_right, w_rbf);
    k_t<<<dim3(64, 4), 128>>>(w_gate);

    cudaFuncSetAttribute(k_main, cudaFuncAttributeMaxDynamicSharedMemorySize, SMTOT);
    k_main<<<dim3(LL, 8), 256, SMTOT>>>(b_rbf, b_gate, out);
}